// round 1
// baseline (speedup 1.0000x reference)
#include <cuda_runtime.h>
#include <math.h>

// Problem constants
#define TT   32
#define BB   32
#define NIN  64
#define HH   256
#define NOUT 64
#define EMAX 9984   // 64 + 31*320 max stored "pre" rows per batch
#define CLMIN (-2.0f)
#define CLMAX ( 2.0f)

// Scratch state (device globals: no allocations allowed)
__device__ float g_buf[2][BB * EMAX * HH];  // ping-pong pre-activation error rows, [b][r][h]
__device__ float g_rad[BB * HH];
__device__ float g_lam[BB * HH];
__device__ float g_delta[BB * HH];
__device__ float g_headpre[BB * HH];
__device__ float g_headpost[BB * HH];
__device__ float g_radout[BB * NOUT];

// ---------------------------------------------------------------------------
// Step 0: build x-block rows (pre_0), rad_0, head_pre_0.  One block per batch.
// ---------------------------------------------------------------------------
__global__ void step0_kernel(const float* __restrict__ X,
                             const float* __restrict__ eps,
                             const float* __restrict__ W_ih,
                             const float* __restrict__ b_ih,
                             const float* __restrict__ b_hh)
{
    int b = blockIdx.x;
    int tid = threadIdx.x;  // 256
    __shared__ float s_hx[NIN], s_w[NIN];
    if (tid < NIN) {
        float x = X[b * NIN + tid];   // t = 0
        float e = eps[b];
        float l = fmaxf(x - e, CLMIN);
        float u = fminf(x + e, CLMAX);
        s_hx[tid] = 0.5f * (l + u);
        s_w[tid]  = 0.5f * (u - l);
    }
    __syncthreads();
    int h = tid;
    float hp = b_ih[h] + b_hh[h];
    float rad = 0.f;
    float* buf = g_buf[0];
#pragma unroll 8
    for (int i = 0; i < NIN; i++) {
        float wv = W_ih[i * HH + h];
        float rowv = s_w[i] * wv;
        hp += s_hx[i] * wv;
        rad += fabsf(rowv);
        buf[((size_t)b * EMAX + i) * HH + h] = rowv;
    }
    g_headpre[b * HH + h] = hp;
    g_rad[b * HH + h] = rad;
}

// ---------------------------------------------------------------------------
// Pointwise DeepZ tanh transformer.  <<<BB, HH>>>
// Produces lam_t, delta_t, head_post_t; zeroes rad for next step.
// ---------------------------------------------------------------------------
__global__ void pointwise_kernel(int zero_radout)
{
    int b = blockIdx.x, h = threadIdx.x;
    int idx = b * HH + h;
    float head = g_headpre[idx];
    float rad  = g_rad[idx];
    float l = head - rad, u = head + rad;
    float tl = tanhf(l), tu = tanhf(u);
    float lam = fminf(1.f - tl * tl, 1.f - tu * tu);
    float mu    = 0.5f * (tu + tl - lam * (u + l));
    float delta = 0.5f * (tu - tl - lam * (u - l));
    g_headpost[idx] = lam * head + mu;
    g_lam[idx]   = lam;
    g_delta[idx] = delta;
    g_rad[idx]   = 0.f;               // ready for next step's atomics
    if (zero_radout && h < NOUT) g_radout[b * NOUT + h] = 0.f;
}

// ---------------------------------------------------------------------------
// Main propagation GEMM: out[b,r,:] = in[b,r,:] @ (diag(lam[b]) W_hh)
// with fused abs-column-sum epilogue into g_rad.
// Tile 128x128, BK=16, 256 threads, 8x8 microtile.
// grid: (ceil(M/128), 2, BB)
// ---------------------------------------------------------------------------
__global__ void __launch_bounds__(256, 2)
gemm_kernel(const float* __restrict__ W_hh, int M, int pp)
{
    int b = blockIdx.z;
    int nbase = blockIdx.y * 128;
    int mbase = blockIdx.x * 128;
    const float* A = g_buf[pp]     + (size_t)b * EMAX * HH;
    float*       O = g_buf[pp ^ 1] + (size_t)b * EMAX * HH;
    const float* lam = g_lam + b * HH;

    __shared__ float sA[16][132];   // k-major, padded
    __shared__ float sB[16][128];

    int tid = threadIdx.x;
    int tx = tid & 15, ty = tid >> 4;
    int arow = tid >> 2, acol = (tid & 3) * 4;
    int bk = tid >> 4, bn = (tid & 15) * 4;

    float acc[8][8];
#pragma unroll
    for (int i = 0; i < 8; i++)
#pragma unroll
        for (int j = 0; j < 8; j++) acc[i][j] = 0.f;

    for (int k0 = 0; k0 < HH; k0 += 16) {
#pragma unroll
        for (int i = 0; i < 2; i++) {
            int r = mbase + arow + i * 64;
            float4 v = make_float4(0.f, 0.f, 0.f, 0.f);
            if (r < M) v = *(const float4*)&A[(size_t)r * HH + k0 + acol];
            sA[acol + 0][arow + i * 64] = v.x;
            sA[acol + 1][arow + i * 64] = v.y;
            sA[acol + 2][arow + i * 64] = v.z;
            sA[acol + 3][arow + i * 64] = v.w;
        }
        float lm = lam[k0 + bk];
#pragma unroll
        for (int i = 0; i < 2; i++) {
            float4 v = *(const float4*)&W_hh[(size_t)(k0 + bk) * HH + nbase + bn + i * 64];
            v.x *= lm; v.y *= lm; v.z *= lm; v.w *= lm;
            *(float4*)&sB[bk][bn + i * 64] = v;
        }
        __syncthreads();
#pragma unroll
        for (int k = 0; k < 16; k++) {
            float a[8], bb[8];
            *(float4*)&a[0]  = *(const float4*)&sA[k][ty * 8];
            *(float4*)&a[4]  = *(const float4*)&sA[k][ty * 8 + 4];
            *(float4*)&bb[0] = *(const float4*)&sB[k][tx * 8];
            *(float4*)&bb[4] = *(const float4*)&sB[k][tx * 8 + 4];
#pragma unroll
            for (int i = 0; i < 8; i++)
#pragma unroll
                for (int j = 0; j < 8; j++) acc[i][j] += a[i] * bb[j];
        }
        __syncthreads();
    }

    // write rows + per-column |.| partials
    float cs[8];
#pragma unroll
    for (int j = 0; j < 8; j++) cs[j] = 0.f;
#pragma unroll
    for (int i = 0; i < 8; i++) {
        int r = mbase + ty * 8 + i;
        if (r < M) {
            *(float4*)&O[(size_t)r * HH + nbase + tx * 8]     = make_float4(acc[i][0], acc[i][1], acc[i][2], acc[i][3]);
            *(float4*)&O[(size_t)r * HH + nbase + tx * 8 + 4] = make_float4(acc[i][4], acc[i][5], acc[i][6], acc[i][7]);
        }
#pragma unroll
        for (int j = 0; j < 8; j++) cs[j] += fabsf(acc[i][j]);  // padded rows are exact zeros
    }
    __syncthreads();
#pragma unroll
    for (int j = 0; j < 8; j++) sB[ty][tx * 8 + j] = cs[j];
    __syncthreads();
    if (tid < 128) {
        float s = 0.f;
#pragma unroll
        for (int r = 0; r < 16; r++) s += sB[r][tid];
        atomicAdd(&g_rad[b * HH + nbase + tid], s);
    }
}

// ---------------------------------------------------------------------------
// Append fresh rows (delta_{t-1} x W_hh), x-block rows, head recurrence and
// their rad contributions.  grid (BB, 10), 256 threads.
// ---------------------------------------------------------------------------
__global__ void append_kernel(const float* __restrict__ X,
                              const float* __restrict__ eps,
                              const float* __restrict__ W_ih,
                              const float* __restrict__ W_hh,
                              const float* __restrict__ b_ih,
                              const float* __restrict__ b_hh,
                              int t, int Eprev, int pp)
{
    int b = blockIdx.x, z = blockIdx.y, tid = threadIdx.x;
    float* out = g_buf[pp ^ 1] + (size_t)b * EMAX * HH;
    const float* Xt = X + (size_t)t * BB * NIN;

    if (z < 8) {
        // fresh diag block rows: out[Eprev+i, h] = delta[b,i] * W_hh[i, h]
        int h = tid;
#pragma unroll 4
        for (int ii = 0; ii < 32; ii++) {
            int i = z * 32 + ii;
            float d = g_delta[b * HH + i];
            out[((size_t)(Eprev + i)) * HH + h] = d * W_hh[i * HH + h];
        }
    } else if (z == 8) {
        // x-block rows: out[Eprev+HH+i, h] = w_t[b,i] * W_ih[i, h]
        __shared__ float s_w[NIN];
        if (tid < NIN) {
            float x = Xt[b * NIN + tid];
            float e = eps[b];
            float l = fmaxf(x - e, CLMIN), u = fminf(x + e, CLMAX);
            s_w[tid] = 0.5f * (u - l);
        }
        __syncthreads();
        int h = tid;
#pragma unroll 8
        for (int i = 0; i < NIN; i++)
            out[((size_t)(Eprev + HH + i)) * HH + h] = s_w[i] * W_ih[i * HH + h];
    } else {
        // head_pre_t and rad contributions of fresh + x blocks
        __shared__ float s_hx[NIN], s_w[NIN], s_hp[HH], s_d[HH];
        if (tid < NIN) {
            float x = Xt[b * NIN + tid];
            float e = eps[b];
            float l = fmaxf(x - e, CLMIN), u = fminf(x + e, CLMAX);
            s_hx[tid] = 0.5f * (l + u);
            s_w[tid]  = 0.5f * (u - l);
        }
        s_hp[tid] = g_headpost[b * HH + tid];
        s_d[tid]  = fabsf(g_delta[b * HH + tid]);
        __syncthreads();
        int h = tid;
        float hp = b_ih[h] + b_hh[h];
        float radc = 0.f;
#pragma unroll 8
        for (int k = 0; k < HH; k++) {
            float wv = W_hh[k * HH + h];
            hp   += s_hp[k] * wv;
            radc += s_d[k] * fabsf(wv);
        }
#pragma unroll 8
        for (int i = 0; i < NIN; i++) {
            float wv = W_ih[i * HH + h];
            hp   += s_hx[i] * wv;
            radc += fabsf(s_w[i]) * fabsf(wv);
        }
        g_headpre[b * HH + h] = hp;
        atomicAdd(&g_rad[b * HH + h], radc);
    }
}

// ---------------------------------------------------------------------------
// Final projection: radout[b,j] += sum_r | pre[b,r,:] @ (diag(lam) W_o)[:,j] |
// Tile 128 rows x 64 cols (full N), full K in-block so abs is valid.
// grid: (M/128, BB), 256 threads, 4x8 microtile.
// ---------------------------------------------------------------------------
__global__ void __launch_bounds__(256, 2)
final_gemm_kernel(const float* __restrict__ W_o, int M, int pp)
{
    int b = blockIdx.y;
    int mbase = blockIdx.x * 128;
    const float* A = g_buf[pp] + (size_t)b * EMAX * HH;
    const float* lam = g_lam + b * HH;

    __shared__ float sA[16][132];
    __shared__ float sW[16][64];

    int tid = threadIdx.x;
    int tx = tid & 7, ty = tid >> 3;        // ty 0..31 -> 4 rows each; tx 0..7 -> 8 cols each
    int arow = tid >> 2, acol = (tid & 3) * 4;
    int wk = tid >> 4, wj = (tid & 15) * 4;

    float acc[4][8];
#pragma unroll
    for (int i = 0; i < 4; i++)
#pragma unroll
        for (int j = 0; j < 8; j++) acc[i][j] = 0.f;

    for (int k0 = 0; k0 < HH; k0 += 16) {
#pragma unroll
        for (int i = 0; i < 2; i++) {
            int r = mbase + arow + i * 64;
            float4 v = make_float4(0.f, 0.f, 0.f, 0.f);
            if (r < M) v = *(const float4*)&A[(size_t)r * HH + k0 + acol];
            sA[acol + 0][arow + i * 64] = v.x;
            sA[acol + 1][arow + i * 64] = v.y;
            sA[acol + 2][arow + i * 64] = v.z;
            sA[acol + 3][arow + i * 64] = v.w;
        }
        {
            float lm = lam[k0 + wk];
            float4 v = *(const float4*)&W_o[(size_t)(k0 + wk) * NOUT + wj];
            v.x *= lm; v.y *= lm; v.z *= lm; v.w *= lm;
            *(float4*)&sW[wk][wj] = v;
        }
        __syncthreads();
#pragma unroll
        for (int k = 0; k < 16; k++) {
            float a[4], w[8];
            *(float4*)&a[0] = *(const float4*)&sA[k][ty * 4];
            *(float4*)&w[0] = *(const float4*)&sW[k][tx * 8];
            *(float4*)&w[4] = *(const float4*)&sW[k][tx * 8 + 4];
#pragma unroll
            for (int i = 0; i < 4; i++)
#pragma unroll
                for (int j = 0; j < 8; j++) acc[i][j] += a[i] * w[j];
        }
        __syncthreads();
    }

    // |dot| summed over this block's rows -> atomics
    float cs[8];
#pragma unroll
    for (int j = 0; j < 8; j++) cs[j] = 0.f;
#pragma unroll
    for (int i = 0; i < 4; i++)
#pragma unroll
        for (int j = 0; j < 8; j++) cs[j] += fabsf(acc[i][j]);

    __shared__ float red[32][64];
#pragma unroll
    for (int j = 0; j < 8; j++) red[ty][tx * 8 + j] = cs[j];
    __syncthreads();
    if (tid < NOUT) {
        float s = 0.f;
#pragma unroll
        for (int r = 0; r < 32; r++) s += red[r][tid];
        atomicAdd(&g_radout[b * NOUT + tid], s);
    }
}

// ---------------------------------------------------------------------------
// Combine: head_out = head_post @ W_o + b_o, add diag(delta_31) term, emit bounds.
// <<<BB, NOUT>>>
// ---------------------------------------------------------------------------
__global__ void combine_kernel(const float* __restrict__ W_o,
                               const float* __restrict__ b_o,
                               float* __restrict__ out)
{
    int b = blockIdx.x, j = threadIdx.x;
    float head = b_o[j];
    float radd = 0.f;
#pragma unroll 8
    for (int k = 0; k < HH; k++) {
        float wv = W_o[k * NOUT + j];
        head += g_headpost[b * HH + k] * wv;
        radd += fabsf(g_delta[b * HH + k]) * fabsf(wv);
    }
    float r = g_radout[b * NOUT + j] + radd;
    out[b * NOUT + j]            = head - r;   // lower
    out[BB * NOUT + b * NOUT + j] = head + r;  // upper
}

// ---------------------------------------------------------------------------
extern "C" void kernel_launch(void* const* d_in, const int* in_sizes, int n_in,
                              void* d_out, int out_size)
{
    const float* X    = (const float*)d_in[0];
    const float* eps  = (const float*)d_in[1];
    const float* W_ih = (const float*)d_in[2];
    const float* W_hh = (const float*)d_in[3];
    const float* b_ih = (const float*)d_in[4];
    const float* b_hh = (const float*)d_in[5];
    const float* W_o  = (const float*)d_in[6];
    const float* b_o  = (const float*)d_in[7];
    float* out = (float*)d_out;

    step0_kernel<<<BB, HH>>>(X, eps, W_ih, b_ih, b_hh);
    pointwise_kernel<<<BB, HH>>>(0);

    int E = NIN;   // stored pre rows per batch
    int pp = 0;
    for (int t = 1; t < TT; t++) {
        dim3 g((E + 127) / 128, 2, BB);
        gemm_kernel<<<g, 256>>>(W_hh, E, pp);
        append_kernel<<<dim3(BB, 10), 256>>>(X, eps, W_ih, W_hh, b_ih, b_hh, t, E, pp);
        pointwise_kernel<<<BB, HH>>>((t == TT - 1) ? 1 : 0);
        E += HH + NIN;
        pp ^= 1;
    }

    // E == 9984 == 78*128
    final_gemm_kernel<<<dim3(E / 128, BB), 256>>>(W_o, E, pp);
    combine_kernel<<<BB, NOUT>>>(W_o, b_o, out);
}

// round 4
// speedup vs baseline: 1.9664x; 1.9664x over previous
#include <cuda_runtime.h>
#include <cuda_bf16.h>
#include <math.h>
#include <stdint.h>

// Problem constants
#define TT   32
#define BB   32
#define NIN  64
#define HH   256
#define NOUT 64
#define EMAX 9984
#define CLMIN (-2.0f)
#define CLMAX ( 2.0f)

// B tile layout: per (n-half, k-chunk16): [128 n-rows][48B pitch] (16 bf16 + 16B pad)
#define BPITCH 48
#define TILEB  (128 * BPITCH)          // 6144 bytes
#define GBSZ   (2 * 16 * TILEB)        // 196608 bytes per hi/lo

// ------- device state (no allocations allowed) -------
__device__ float g_buf[2][BB * EMAX * HH];   // ping-pong PRE-activation error rows
__device__ float g_rad[BB * HH];
__device__ float g_lam[BB * HH];
__device__ float g_delta[BB * HH];
__device__ float g_headpre[BB * HH];
__device__ float g_headpost[BB * HH];
__device__ float g_radout[BB * NOUT];
__device__ unsigned char g_Bhi[GBSZ];
__device__ unsigned char g_Blo[GBSZ];

// ------- helpers -------
__device__ __forceinline__ uint32_t smem_u32(const void* p) {
    uint32_t a;
    asm("{ .reg .u64 t; cvta.to.shared.u64 t, %1; cvt.u32.u64 %0, t; }" : "=r"(a) : "l"(p));
    return a;
}
__device__ __forceinline__ void ldsm4(unsigned r[4], uint32_t addr) {
    asm volatile("ldmatrix.sync.aligned.m8n8.x4.shared.b16 {%0,%1,%2,%3}, [%4];"
                 : "=r"(r[0]), "=r"(r[1]), "=r"(r[2]), "=r"(r[3]) : "r"(addr));
}
__device__ __forceinline__ void mma_bf16(float* c, const unsigned a[4],
                                         unsigned b0, unsigned b1) {
    asm volatile("mma.sync.aligned.m16n8k16.row.col.f32.bf16.bf16.f32 "
                 "{%0,%1,%2,%3},{%4,%5,%6,%7},{%8,%9},{%0,%1,%2,%3};"
                 : "+f"(c[0]), "+f"(c[1]), "+f"(c[2]), "+f"(c[3])
                 : "r"(a[0]), "r"(a[1]), "r"(a[2]), "r"(a[3]), "r"(b0), "r"(b1));
}

// SMEM layout (dynamic): sA[buf][hi/lo] 4*6144, sB[buf][hi/lo] 4*6144, lam 1KB
#define SM_A    0
#define SM_B    24576
#define SM_LAM  49152
#define SM_TOT  50176

// ---------------------------------------------------------------------------
// Prep: W_hh^T -> bf16 hi/lo in ldmatrix-friendly tiles (pitch 48)
// ---------------------------------------------------------------------------
__global__ void prepB_kernel(const float* __restrict__ W_hh)
{
    int idx = blockIdx.x * 256 + threadIdx.x;   // 65536
    int k = idx >> 8, n = idx & 255;
    float v = W_hh[k * HH + n];
    __nv_bfloat16 h = __float2bfloat16_rn(v);
    __nv_bfloat16 l = __float2bfloat16_rn(v - __bfloat162float(h));
    int half = n >> 7, c = k >> 4, nl = n & 127, kl = k & 15;
    uint32_t off = (uint32_t)(((half * 16 + c) * 128 + nl) * BPITCH + kl * 2);
    *(__nv_bfloat16*)(g_Bhi + off) = h;
    *(__nv_bfloat16*)(g_Blo + off) = l;
}

// ---------------------------------------------------------------------------
// Step 0
// ---------------------------------------------------------------------------
__global__ void step0_kernel(const float* __restrict__ X,
                             const float* __restrict__ eps,
                             const float* __restrict__ W_ih,
                             const float* __restrict__ b_ih,
                             const float* __restrict__ b_hh)
{
    int b = blockIdx.x;
    int tid = threadIdx.x;
    __shared__ float s_hx[NIN], s_w[NIN];
    if (tid < NIN) {
        float x = X[b * NIN + tid];
        float e = eps[b];
        float l = fmaxf(x - e, CLMIN);
        float u = fminf(x + e, CLMAX);
        s_hx[tid] = 0.5f * (l + u);
        s_w[tid]  = 0.5f * (u - l);
    }
    __syncthreads();
    int h = tid;
    float hp = b_ih[h] + b_hh[h];
    float rad = 0.f;
    float* buf = g_buf[0];
#pragma unroll 8
    for (int i = 0; i < NIN; i++) {
        float wv = W_ih[i * HH + h];
        float rowv = s_w[i] * wv;
        hp += s_hx[i] * wv;
        rad += fabsf(rowv);
        buf[((size_t)b * EMAX + i) * HH + h] = rowv;
    }
    g_headpre[b * HH + h] = hp;
    g_rad[b * HH + h] = rad;
}

// ---------------------------------------------------------------------------
// Pointwise DeepZ tanh transformer
// ---------------------------------------------------------------------------
__global__ void pointwise_kernel(int zero_radout)
{
    int b = blockIdx.x, h = threadIdx.x;
    int idx = b * HH + h;
    float head = g_headpre[idx];
    float rad  = g_rad[idx];
    float l = head - rad, u = head + rad;
    float tl = tanhf(l), tu = tanhf(u);
    float lam = fminf(1.f - tl * tl, 1.f - tu * tu);
    float mu    = 0.5f * (tu + tl - lam * (u + l));
    float delta = 0.5f * (tu - tl - lam * (u - l));
    g_headpost[idx] = lam * head + mu;
    g_lam[idx]   = lam;
    g_delta[idx] = delta;
    g_rad[idx]   = 0.f;
    if (zero_radout && h < NOUT) g_radout[b * NOUT + h] = 0.f;
}

// ---------------------------------------------------------------------------
// HMMA propagation GEMM: out[b,r,:] = (in[b,r,:]*lam[b,:]) @ W_hh
// bf16 hi/lo 3-pass, fused |.| colsum. grid (ceil(M/128), 2, BB), 256 thr.
// ---------------------------------------------------------------------------
__global__ void __launch_bounds__(256, 2)
gemm_mma_kernel(int M, int pp)
{
    extern __shared__ char sm[];
    uint32_t smb = smem_u32(sm);

    int b = blockIdx.z;
    int nhalf = blockIdx.y;
    int nbase = nhalf * 128;
    int mbase = blockIdx.x * 128;
    const float* A = g_buf[pp]     + (size_t)b * EMAX * HH;
    float*       O = g_buf[pp ^ 1] + (size_t)b * EMAX * HH;

    int tid = threadIdx.x;
    int w = tid >> 5, lane = tid & 31;
    float* lam_s = (float*)(sm + SM_LAM);
    if (tid < 64) ((float4*)lam_s)[tid] = ((const float4*)(g_lam + b * HH))[tid];

    // A staging: thread handles groups g=tid, tid+256; row=g>>2, q=g&3 (4 floats)
    float4 areg[2];
    uint4  breg[3];
    int bpart = tid >> 7;            // 0: hi, 1: lo
    int bpoff = (tid & 127) * 3;     // uint4 index in tile

    const uint4* srcH = (const uint4*)(g_Bhi + (size_t)nhalf * 16 * TILEB);
    const uint4* srcL = (const uint4*)(g_Blo + (size_t)nhalf * 16 * TILEB);

#define LOAD_CHUNK(c) do {                                                     \
    _Pragma("unroll")                                                          \
    for (int i = 0; i < 2; i++) {                                              \
        int g = tid + i * 256, row = g >> 2, q = g & 3;                        \
        int r = mbase + row;                                                   \
        areg[i] = (r < M) ? *(const float4*)&A[(size_t)r * HH + (c) * 16 + q * 4] \
                          : make_float4(0.f, 0.f, 0.f, 0.f);                   \
    }                                                                          \
    const uint4* bs = bpart ? srcL : srcH;                                     \
    _Pragma("unroll")                                                          \
    for (int j = 0; j < 3; j++) breg[j] = bs[(size_t)(c) * 384 + bpoff + j];   \
} while (0)

#define STORE_CHUNK(c, buf) do {                                               \
    _Pragma("unroll")                                                          \
    for (int i = 0; i < 2; i++) {                                              \
        int g = tid + i * 256, row = g >> 2, q = g & 3;                        \
        float4 v = areg[i];                                                    \
        int kb = (c) * 16 + q * 4;                                             \
        v.x *= lam_s[kb]; v.y *= lam_s[kb + 1];                                \
        v.z *= lam_s[kb + 2]; v.w *= lam_s[kb + 3];                            \
        __nv_bfloat162 h01 = __floats2bfloat162_rn(v.x, v.y);                  \
        __nv_bfloat162 h23 = __floats2bfloat162_rn(v.z, v.w);                  \
        __nv_bfloat162 l01 = __floats2bfloat162_rn(                            \
            v.x - __bfloat162float(h01.x), v.y - __bfloat162float(h01.y));     \
        __nv_bfloat162 l23 = __floats2bfloat162_rn(                            \
            v.z - __bfloat162float(h23.x), v.w - __bfloat162float(h23.y));     \
        uint32_t ao = (uint32_t)(((buf) * 2) * TILEB + row * BPITCH + q * 8);  \
        *(uint2*)(sm + SM_A + ao)         = make_uint2(*(uint32_t*)&h01, *(uint32_t*)&h23); \
        *(uint2*)(sm + SM_A + ao + TILEB) = make_uint2(*(uint32_t*)&l01, *(uint32_t*)&l23); \
    }                                                                          \
    uint4* bd = (uint4*)(sm + SM_B + ((buf) * 2 + bpart) * TILEB);             \
    _Pragma("unroll")                                                          \
    for (int j = 0; j < 3; j++) bd[bpoff + j] = breg[j];                       \
} while (0)

    float acc[2][8][4];
#pragma unroll
    for (int mt = 0; mt < 2; mt++)
#pragma unroll
        for (int nt = 0; nt < 8; nt++)
#pragma unroll
            for (int e = 0; e < 4; e++) acc[mt][nt][e] = 0.f;

    LOAD_CHUNK(0);
    STORE_CHUNK(0, 0);
    __syncthreads();

    int wm = w >> 1, wn = w & 1;
    uint32_t aLane = (uint32_t)((wm * 32 + (lane & 15)) * BPITCH + ((lane >> 4) << 4));
    uint32_t bLane = (uint32_t)((wn * 64 + (lane & 15)) * BPITCH + ((lane >> 4) << 4));

    for (int c = 0; c < 16; c++) {
        int buf = c & 1;
        if (c < 15) LOAD_CHUNK(c + 1);

        uint32_t aHi = smb + SM_A + (buf * 2) * TILEB + aLane;
        uint32_t bHi = smb + SM_B + (buf * 2) * TILEB + bLane;

        unsigned ah[2][4], al[2][4];
#pragma unroll
        for (int mt = 0; mt < 2; mt++) {
            ldsm4(ah[mt], aHi + mt * (16 * BPITCH));
            ldsm4(al[mt], aHi + mt * (16 * BPITCH) + TILEB);
        }
#pragma unroll
        for (int p = 0; p < 4; p++) {
            unsigned bh[4], bl[4];
            ldsm4(bh, bHi + p * (16 * BPITCH));
            ldsm4(bl, bHi + p * (16 * BPITCH) + TILEB);
#pragma unroll
            for (int mt = 0; mt < 2; mt++) {
                mma_bf16(acc[mt][2 * p],     ah[mt], bh[0], bh[2]);
                mma_bf16(acc[mt][2 * p],     ah[mt], bl[0], bl[2]);
                mma_bf16(acc[mt][2 * p],     al[mt], bh[0], bh[2]);
                mma_bf16(acc[mt][2 * p + 1], ah[mt], bh[1], bh[3]);
                mma_bf16(acc[mt][2 * p + 1], ah[mt], bl[1], bl[3]);
                mma_bf16(acc[mt][2 * p + 1], al[mt], bh[1], bh[3]);
            }
        }
        if (c < 15) {
            STORE_CHUNK(c + 1, buf ^ 1);
            __syncthreads();
        }
    }

    // ---- epilogue: write rows + |.| column sums ----
    float pc[8][2];
#pragma unroll
    for (int nt = 0; nt < 8; nt++) { pc[nt][0] = 0.f; pc[nt][1] = 0.f; }

#pragma unroll
    for (int mt = 0; mt < 2; mt++) {
#pragma unroll
        for (int rr = 0; rr < 2; rr++) {
            int row = mbase + wm * 32 + mt * 16 + rr * 8 + (lane >> 2);
            bool ok = (row < M);
#pragma unroll
            for (int nt = 0; nt < 8; nt++) {
                float v0 = acc[mt][nt][rr * 2], v1 = acc[mt][nt][rr * 2 + 1];
                if (ok) {
                    int col = nbase + wn * 64 + nt * 8 + (lane & 3) * 2;
                    *(float2*)&O[(size_t)row * HH + col] = make_float2(v0, v1);
                }
                pc[nt][0] += fabsf(v0);
                pc[nt][1] += fabsf(v1);
            }
        }
    }
#pragma unroll
    for (int nt = 0; nt < 8; nt++) {
#pragma unroll
        for (int j = 0; j < 2; j++) {
            float s = pc[nt][j];
            s += __shfl_xor_sync(0xFFFFFFFFu, s, 4);
            s += __shfl_xor_sync(0xFFFFFFFFu, s, 8);
            s += __shfl_xor_sync(0xFFFFFFFFu, s, 16);
            pc[nt][j] = s;
        }
    }
    if (lane < 4) {
#pragma unroll
        for (int nt = 0; nt < 8; nt++)
#pragma unroll
            for (int j = 0; j < 2; j++)
                atomicAdd(&g_rad[b * HH + nbase + wn * 64 + nt * 8 + lane * 2 + j],
                          pc[nt][j]);
    }
#undef LOAD_CHUNK
#undef STORE_CHUNK
}

// ---------------------------------------------------------------------------
// Append fresh rows + head recurrence
// ---------------------------------------------------------------------------
__global__ void append_kernel(const float* __restrict__ X,
                              const float* __restrict__ eps,
                              const float* __restrict__ W_ih,
                              const float* __restrict__ W_hh,
                              const float* __restrict__ b_ih,
                              const float* __restrict__ b_hh,
                              int t, int Eprev, int pp)
{
    int b = blockIdx.x, z = blockIdx.y, tid = threadIdx.x;
    float* out = g_buf[pp ^ 1] + (size_t)b * EMAX * HH;
    const float* Xt = X + (size_t)t * BB * NIN;

    if (z < 8) {
        int h = tid;
#pragma unroll 4
        for (int ii = 0; ii < 32; ii++) {
            int i = z * 32 + ii;
            float d = g_delta[b * HH + i];
            out[((size_t)(Eprev + i)) * HH + h] = d * W_hh[i * HH + h];
        }
    } else if (z == 8) {
        __shared__ float s_w[NIN];
        if (tid < NIN) {
            float x = Xt[b * NIN + tid];
            float e = eps[b];
            float l = fmaxf(x - e, CLMIN), u = fminf(x + e, CLMAX);
            s_w[tid] = 0.5f * (u - l);
        }
        __syncthreads();
        int h = tid;
#pragma unroll 8
        for (int i = 0; i < NIN; i++)
            out[((size_t)(Eprev + HH + i)) * HH + h] = s_w[i] * W_ih[i * HH + h];
    } else {
        __shared__ float s_hx[NIN], s_w[NIN], s_hp[HH], s_d[HH];
        if (tid < NIN) {
            float x = Xt[b * NIN + tid];
            float e = eps[b];
            float l = fmaxf(x - e, CLMIN), u = fminf(x + e, CLMAX);
            s_hx[tid] = 0.5f * (l + u);
            s_w[tid]  = 0.5f * (u - l);
        }
        s_hp[tid] = g_headpost[b * HH + tid];
        s_d[tid]  = fabsf(g_delta[b * HH + tid]);
        __syncthreads();
        int h = tid;
        float hp = b_ih[h] + b_hh[h];
        float radc = 0.f;
#pragma unroll 8
        for (int k = 0; k < HH; k++) {
            float wv = W_hh[k * HH + h];
            hp   += s_hp[k] * wv;
            radc += s_d[k] * fabsf(wv);
        }
#pragma unroll 8
        for (int i = 0; i < NIN; i++) {
            float wv = W_ih[i * HH + h];
            hp   += s_hx[i] * wv;
            radc += fabsf(s_w[i]) * fabsf(wv);
        }
        g_headpre[b * HH + h] = hp;
        atomicAdd(&g_rad[b * HH + h], radc);
    }
}

// ---------------------------------------------------------------------------
// Final projection (fp32 SIMT)
// ---------------------------------------------------------------------------
__global__ void __launch_bounds__(256, 2)
final_gemm_kernel(const float* __restrict__ W_o, int M, int pp)
{
    int b = blockIdx.y;
    int mbase = blockIdx.x * 128;
    const float* A = g_buf[pp] + (size_t)b * EMAX * HH;
    const float* lam = g_lam + b * HH;

    __shared__ float sA[16][132];
    __shared__ float sW[16][64];

    int tid = threadIdx.x;
    int tx = tid & 7, ty = tid >> 3;
    int arow = tid >> 2, acol = (tid & 3) * 4;
    int wk = tid >> 4, wj = (tid & 15) * 4;

    float acc[4][8];
#pragma unroll
    for (int i = 0; i < 4; i++)
#pragma unroll
        for (int j = 0; j < 8; j++) acc[i][j] = 0.f;

    for (int k0 = 0; k0 < HH; k0 += 16) {
#pragma unroll
        for (int i = 0; i < 2; i++) {
            int r = mbase + arow + i * 64;
            float4 v = make_float4(0.f, 0.f, 0.f, 0.f);
            if (r < M) v = *(const float4*)&A[(size_t)r * HH + k0 + acol];
            sA[acol + 0][arow + i * 64] = v.x;
            sA[acol + 1][arow + i * 64] = v.y;
            sA[acol + 2][arow + i * 64] = v.z;
            sA[acol + 3][arow + i * 64] = v.w;
        }
        {
            float lm = lam[k0 + wk];
            float4 v = *(const float4*)&W_o[(size_t)(k0 + wk) * NOUT + wj];
            v.x *= lm; v.y *= lm; v.z *= lm; v.w *= lm;
            *(float4*)&sW[wk][wj] = v;
        }
        __syncthreads();
#pragma unroll
        for (int k = 0; k < 16; k++) {
            float a[4], wv[8];
            *(float4*)&a[0] = *(const float4*)&sA[k][ty * 4];
            *(float4*)&wv[0] = *(const float4*)&sW[k][tx * 8];
            *(float4*)&wv[4] = *(const float4*)&sW[k][tx * 8 + 4];
#pragma unroll
            for (int i = 0; i < 4; i++)
#pragma unroll
                for (int j = 0; j < 8; j++) acc[i][j] += a[i] * wv[j];
        }
        __syncthreads();
    }

    float cs[8];
#pragma unroll
    for (int j = 0; j < 8; j++) cs[j] = 0.f;
#pragma unroll
    for (int i = 0; i < 4; i++)
#pragma unroll
        for (int j = 0; j < 8; j++) cs[j] += fabsf(acc[i][j]);

    __shared__ float red[32][64];
#pragma unroll
    for (int j = 0; j < 8; j++) red[ty][tx * 8 + j] = cs[j];
    __syncthreads();
    if (tid < NOUT) {
        float s = 0.f;
#pragma unroll
        for (int r = 0; r < 32; r++) s += red[r][tid];
        atomicAdd(&g_radout[b * NOUT + tid], s);
    }
}

// ---------------------------------------------------------------------------
// Combine
// ---------------------------------------------------------------------------
__global__ void combine_kernel(const float* __restrict__ W_o,
                               const float* __restrict__ b_o,
                               float* __restrict__ out)
{
    int b = blockIdx.x, j = threadIdx.x;
    float head = b_o[j];
    float radd = 0.f;
#pragma unroll 8
    for (int k = 0; k < HH; k++) {
        float wv = W_o[k * NOUT + j];
        head += g_headpost[b * HH + k] * wv;
        radd += fabsf(g_delta[b * HH + k]) * fabsf(wv);
    }
    float r = g_radout[b * NOUT + j] + radd;
    out[b * NOUT + j]             = head - r;
    out[BB * NOUT + b * NOUT + j] = head + r;
}

// ---------------------------------------------------------------------------
extern "C" void kernel_launch(void* const* d_in, const int* in_sizes, int n_in,
                              void* d_out, int out_size)
{
    const float* X    = (const float*)d_in[0];
    const float* eps  = (const float*)d_in[1];
    const float* W_ih = (const float*)d_in[2];
    const float* W_hh = (const float*)d_in[3];
    const float* b_ih = (const float*)d_in[4];
    const float* b_hh = (const float*)d_in[5];
    const float* W_o  = (const float*)d_in[6];
    const float* b_o  = (const float*)d_in[7];
    float* out = (float*)d_out;

    cudaFuncSetAttribute(gemm_mma_kernel,
                         cudaFuncAttributeMaxDynamicSharedMemorySize, SM_TOT);

    prepB_kernel<<<256, 256>>>(W_hh);
    step0_kernel<<<BB, HH>>>(X, eps, W_ih, b_ih, b_hh);
    pointwise_kernel<<<BB, HH>>>(0);

    int E = NIN;
    int pp = 0;
    for (int t = 1; t < TT; t++) {
        dim3 g((E + 127) / 128, 2, BB);
        gemm_mma_kernel<<<g, 256, SM_TOT>>>(E, pp);
        append_kernel<<<dim3(BB, 10), 256>>>(X, eps, W_ih, W_hh, b_ih, b_hh, t, E, pp);
        pointwise_kernel<<<BB, HH>>>((t == TT - 1) ? 1 : 0);
        E += HH + NIN;
        pp ^= 1;
    }

    final_gemm_kernel<<<dim3((E + 127) / 128, BB), 256>>>(W_o, E, pp);
    combine_kernel<<<BB, NOUT>>>(W_o, b_o, out);
}

// round 5
// speedup vs baseline: 3.5903x; 1.8258x over previous
#include <cuda_runtime.h>
#include <cuda_fp16.h>
#include <math.h>
#include <stdint.h>

// Problem constants
#define TT   32
#define BB   32
#define NIN  64
#define HH   256
#define NOUT 64
#define EMAX 9984          // 78 * 128 exactly
#define NTILES 78
#define CLMIN (-2.0f)
#define CLMAX ( 2.0f)

// ------- device state (no allocations allowed) -------
// Error-row state, fp16, tiled layout:
//   idx(tile, chunk, row, h) = ((tile*16 + chunk)*128 + row)*16 + h
// (tile = 128 rows, chunk = 16 k-columns, h = column within chunk)
__device__ __half g_state[2][(size_t)BB * EMAX * HH];
// Per-(batch,step) B' = fp16(lam ⊙ W_hh^T), smem-image layout (pitch 24 halves):
//   idx = ((b*2 + nhalf)*16 + chunk)*3072 + nrow*24 + kh
__device__ __half g_Bp[(size_t)BB * 2 * 16 * 3072];
__device__ float g_rad[2][BB * HH];     // parity ping-pong accumulators
__device__ float g_lam[BB * HH];
__device__ float g_delta[BB * HH];
__device__ float g_headpre[BB * HH];
__device__ float g_headpost[BB * HH];
__device__ float g_radout[BB * NOUT];

// ------- helpers -------
__device__ __forceinline__ uint32_t smem_u32(const void* p) {
    uint32_t a;
    asm("{ .reg .u64 t; cvta.to.shared.u64 t, %1; cvt.u32.u64 %0, t; }" : "=r"(a) : "l"(p));
    return a;
}
__device__ __forceinline__ void ldsm4(unsigned r[4], uint32_t addr) {
    asm volatile("ldmatrix.sync.aligned.m8n8.x4.shared.b16 {%0,%1,%2,%3}, [%4];"
                 : "=r"(r[0]), "=r"(r[1]), "=r"(r[2]), "=r"(r[3]) : "r"(addr));
}
__device__ __forceinline__ void mma_f16(float* c, const unsigned a[4],
                                        unsigned b0, unsigned b1) {
    asm volatile("mma.sync.aligned.m16n8k16.row.col.f32.f16.f16.f32 "
                 "{%0,%1,%2,%3},{%4,%5,%6,%7},{%8,%9},{%0,%1,%2,%3};"
                 : "+f"(c[0]), "+f"(c[1]), "+f"(c[2]), "+f"(c[3])
                 : "r"(a[0]), "r"(a[1]), "r"(a[2]), "r"(a[3]), "r"(b0), "r"(b1));
}
__device__ __forceinline__ void cpa16(uint32_t dst, const void* src) {
    asm volatile("cp.async.cg.shared.global [%0], [%1], 16;" :: "r"(dst), "l"(src));
}

#define TILE_BYTES 6144      // 128 rows * 48B pitch
#define STG_BYTES  12288     // A tile + B tile per stage
#define GT_SMEM    (3 * STG_BYTES)

// ---------------------------------------------------------------------------
// Step 0: initial x-block rows (fp16 tiled), head_pre_0, rad[0]
// ---------------------------------------------------------------------------
__global__ void step0_kernel(const float* __restrict__ X,
                             const float* __restrict__ eps,
                             const float* __restrict__ W_ih,
                             const float* __restrict__ b_ih,
                             const float* __restrict__ b_hh)
{
    int b = blockIdx.x;
    int tid = threadIdx.x;  // 256 -> h
    __shared__ float s_hx[NIN], s_w[NIN];
    if (tid < NIN) {
        float x = X[b * NIN + tid];
        float e = eps[b];
        float l = fmaxf(x - e, CLMIN);
        float u = fminf(x + e, CLMAX);
        s_hx[tid] = 0.5f * (l + u);
        s_w[tid]  = 0.5f * (u - l);
    }
    __syncthreads();
    int h = tid;
    float hp = b_ih[h] + b_hh[h];
    float rad = 0.f;
    __half* st = g_state[0] + (size_t)b * EMAX * HH;
    int chunk = h >> 4, kh = h & 15;
#pragma unroll 8
    for (int i = 0; i < NIN; i++) {
        float wv = W_ih[i * HH + h];
        float rowv = s_w[i] * wv;
        hp += s_hx[i] * wv;
        __half hv = __float2half_rn(rowv);
        rad += fabsf(__half2float(hv));
        st[((size_t)chunk * 128 + i) * 16 + kh] = hv;   // tile 0
    }
    g_headpre[b * HH + h] = hp;
    g_rad[0][b * HH + h] = rad;
}

// ---------------------------------------------------------------------------
// post_kernel: fused DeepZ tanh transformer + per-batch B' prep.
// grid (BB, 9), 256 threads.
//   z==8 : lam/delta/headpost from rad[par]; zero rad[par^1]; opt zero radout
//   z<8  : B'[b] tile fill for k in [z*32, z*32+32) (recomputes lam locally)
// ---------------------------------------------------------------------------
__global__ void post_kernel(const float* __restrict__ W_hh, int par, int zero_radout)
{
    int b = blockIdx.x, z = blockIdx.y, tid = threadIdx.x;
    if (z == 8) {
        int idx = b * HH + tid;
        float head = g_headpre[idx];
        float rad  = g_rad[par][idx];
        float l = head - rad, u = head + rad;
        float tl = tanhf(l), tu = tanhf(u);
        float lam = fminf(1.f - tl * tl, 1.f - tu * tu);
        float mu    = 0.5f * (tu + tl - lam * (u + l));
        float delta = 0.5f * (tu - tl - lam * (u - l));
        g_headpost[idx] = lam * head + mu;
        g_lam[idx]   = lam;
        g_delta[idx] = delta;
        g_rad[par ^ 1][idx] = 0.f;
        if (zero_radout && tid < NOUT) g_radout[b * NOUT + tid] = 0.f;
    } else {
        __shared__ float s_lam[32];
        if (tid < 32) {
            int k = z * 32 + tid;
            float head = g_headpre[b * HH + k];
            float rad  = g_rad[par][b * HH + k];
            float l = head - rad, u = head + rad;
            float tl = tanhf(l), tu = tanhf(u);
            s_lam[tid] = fminf(1.f - tl * tl, 1.f - tu * tu);
        }
        __syncthreads();
        int n = tid;
        int nh = n >> 7, row = n & 127;
#pragma unroll 4
        for (int i = 0; i < 32; i++) {
            int k = z * 32 + i;
            float v = s_lam[i] * W_hh[k * HH + n];
            g_Bp[((size_t)(b * 2 + nh) * 16 + (k >> 4)) * 3072 + row * 24 + (k & 15)]
                = __float2half_rn(v);
        }
    }
}

// ---------------------------------------------------------------------------
// Single-pass fp16 propagation GEMM with cp.async 3-stage pipeline.
// out[b,r,:] = in[b,r,:] @ B'[b]   (B' = lam ⊙ W_hh, prepped)
// fused |.| colsum -> g_rad[par]. grid (ceil(M/128), 2, BB), 256 thr.
// ---------------------------------------------------------------------------
__global__ void __launch_bounds__(256, 2)
gemm_mma_kernel(int M, int pp, int par)
{
    extern __shared__ char sm[];
    uint32_t smb = smem_u32(sm);

    int b = blockIdx.z;
    int nhalf = blockIdx.y;
    int nbase = nhalf * 128;
    int mtile = blockIdx.x;
    int mbase = mtile * 128;
    const __half* A = g_state[pp]     + (size_t)b * EMAX * HH;
    __half*       O = g_state[pp ^ 1] + (size_t)b * EMAX * HH;
    const __half* Bp = g_Bp + (size_t)(b * 2 + nhalf) * 16 * 3072;

    int tid = threadIdx.x;
    int w = tid >> 5, lane = tid & 31;

    int aRow = tid >> 1, aHalf = tid & 1;
    int bRow0 = tid / 3, bPart0 = tid - bRow0 * 3;
    int g1 = 256 + tid;
    int bRow1 = g1 / 3, bPart1 = g1 - bRow1 * 3;

#define ISSUE(c) do {                                                          \
    int _s = (c) % 3;                                                          \
    uint32_t _sa = smb + _s * STG_BYTES;                                       \
    cpa16(_sa + aRow * 48 + aHalf * 16,                                        \
          A + (((size_t)mtile * 16 + (c)) * 128 + aRow) * 16 + aHalf * 8);     \
    uint32_t _sb = _sa + TILE_BYTES;                                           \
    cpa16(_sb + bRow0 * 48 + bPart0 * 16,                                      \
          Bp + (size_t)(c) * 3072 + bRow0 * 24 + bPart0 * 8);                  \
    if (tid < 128)                                                             \
        cpa16(_sb + bRow1 * 48 + bPart1 * 16,                                  \
              Bp + (size_t)(c) * 3072 + bRow1 * 24 + bPart1 * 8);              \
    asm volatile("cp.async.commit_group;");                                    \
} while (0)

    float acc[2][8][4];
#pragma unroll
    for (int mt = 0; mt < 2; mt++)
#pragma unroll
        for (int nt = 0; nt < 8; nt++)
#pragma unroll
            for (int e = 0; e < 4; e++) acc[mt][nt][e] = 0.f;

    ISSUE(0);
    ISSUE(1);

    int wm = w >> 1, wn = w & 1;
    uint32_t aL = (uint32_t)((wm * 32 + (lane & 15)) * 48 + ((lane >> 4) << 4));
    uint32_t bL = (uint32_t)((wn * 64 + (lane & 15)) * 48 + ((lane >> 4) << 4));

    for (int c = 0; c < 16; c++) {
        asm volatile("cp.async.wait_group 1;");
        __syncthreads();
        if (c < 14) ISSUE(c + 2);

        int s = c % 3;
        uint32_t aB = smb + s * STG_BYTES + aL;
        uint32_t bB = smb + s * STG_BYTES + TILE_BYTES + bL;

        unsigned af[2][4];
        ldsm4(af[0], aB);
        ldsm4(af[1], aB + 16 * 48);
#pragma unroll
        for (int p = 0; p < 4; p++) {
            unsigned bf[4];
            ldsm4(bf, bB + p * (16 * 48));
#pragma unroll
            for (int mt = 0; mt < 2; mt++) {
                mma_f16(acc[mt][2 * p],     af[mt], bf[0], bf[2]);
                mma_f16(acc[mt][2 * p + 1], af[mt], bf[1], bf[3]);
            }
        }
    }
#undef ISSUE

    // ---- epilogue: fp16 tiled stores + masked |.| column sums ----
    float pc[8][2];
#pragma unroll
    for (int nt = 0; nt < 8; nt++) { pc[nt][0] = 0.f; pc[nt][1] = 0.f; }

#pragma unroll
    for (int mt = 0; mt < 2; mt++) {
#pragma unroll
        for (int rr = 0; rr < 2; rr++) {
            int rIn = wm * 32 + mt * 16 + rr * 8 + (lane >> 2);
            int row = mbase + rIn;
            bool ok = (row < M);
#pragma unroll
            for (int nt = 0; nt < 8; nt++) {
                float v0 = acc[mt][nt][rr * 2], v1 = acc[mt][nt][rr * 2 + 1];
                if (ok) {
                    int col = nbase + wn * 64 + nt * 8 + (lane & 3) * 2;
                    __half2 hv = __floats2half2_rn(v0, v1);
                    *(__half2*)&O[(((size_t)mtile * 16 + (col >> 4)) * 128 + rIn) * 16
                                  + (col & 15)] = hv;
                    pc[nt][0] += fabsf(v0);
                    pc[nt][1] += fabsf(v1);
                }
            }
        }
    }
#pragma unroll
    for (int nt = 0; nt < 8; nt++) {
#pragma unroll
        for (int j = 0; j < 2; j++) {
            float s = pc[nt][j];
            s += __shfl_xor_sync(0xFFFFFFFFu, s, 4);
            s += __shfl_xor_sync(0xFFFFFFFFu, s, 8);
            s += __shfl_xor_sync(0xFFFFFFFFu, s, 16);
            pc[nt][j] = s;
        }
    }
    if (lane < 4) {
#pragma unroll
        for (int nt = 0; nt < 8; nt++)
#pragma unroll
            for (int j = 0; j < 2; j++)
                atomicAdd(&g_rad[par][b * HH + nbase + wn * 64 + nt * 8 + lane * 2 + j],
                          pc[nt][j]);
    }
}

// ---------------------------------------------------------------------------
// Append fresh + x rows (fp16 tiled), head recurrence + their rad parts.
// grid (BB, 10), 256 threads.
// ---------------------------------------------------------------------------
__global__ void append_kernel(const float* __restrict__ X,
                              const float* __restrict__ eps,
                              const float* __restrict__ W_ih,
                              const float* __restrict__ W_hh,
                              const float* __restrict__ b_ih,
                              const float* __restrict__ b_hh,
                              int t, int Eprev, int pp, int par)
{
    int b = blockIdx.x, z = blockIdx.y, tid = threadIdx.x;
    __half* out = g_state[pp ^ 1] + (size_t)b * EMAX * HH;
    const float* Xt = X + (size_t)t * BB * NIN;

    if (z < 8) {
        // fresh diag rows: out[Eprev+i, h] = fp16(delta_i * W_hh[i, h])
        int h = tid;
        int chunk = h >> 4, kh = h & 15;
#pragma unroll 4
        for (int ii = 0; ii < 32; ii++) {
            int i = z * 32 + ii;
            int R = Eprev + i;
            float d = g_delta[b * HH + i];
            out[(((size_t)(R >> 7) * 16 + chunk) * 128 + (R & 127)) * 16 + kh]
                = __float2half_rn(d * W_hh[i * HH + h]);
        }
    } else if (z == 8) {
        __shared__ float s_w[NIN];
        if (tid < NIN) {
            float x = Xt[b * NIN + tid];
            float e = eps[b];
            float l = fmaxf(x - e, CLMIN), u = fminf(x + e, CLMAX);
            s_w[tid] = 0.5f * (u - l);
        }
        __syncthreads();
        int h = tid;
        int chunk = h >> 4, kh = h & 15;
#pragma unroll 8
        for (int i = 0; i < NIN; i++) {
            int R = Eprev + HH + i;
            out[(((size_t)(R >> 7) * 16 + chunk) * 128 + (R & 127)) * 16 + kh]
                = __float2half_rn(s_w[i] * W_ih[i * HH + h]);
        }
    } else {
        // head_pre_t + rad contributions of fresh + x blocks (fp32)
        __shared__ float s_hx[NIN], s_w[NIN], s_hp[HH], s_d[HH];
        if (tid < NIN) {
            float x = Xt[b * NIN + tid];
            float e = eps[b];
            float l = fmaxf(x - e, CLMIN), u = fminf(x + e, CLMAX);
            s_hx[tid] = 0.5f * (l + u);
            s_w[tid]  = 0.5f * (u - l);
        }
        s_hp[tid] = g_headpost[b * HH + tid];
        s_d[tid]  = fabsf(g_delta[b * HH + tid]);
        __syncthreads();
        int h = tid;
        float hp = b_ih[h] + b_hh[h];
        float radc = 0.f;
#pragma unroll 8
        for (int k = 0; k < HH; k++) {
            float wv = W_hh[k * HH + h];
            hp   += s_hp[k] * wv;
            radc += s_d[k] * fabsf(wv);
        }
#pragma unroll 8
        for (int i = 0; i < NIN; i++) {
            float wv = W_ih[i * HH + h];
            hp   += s_hx[i] * wv;
            radc += fabsf(s_w[i]) * fabsf(wv);
        }
        g_headpre[b * HH + h] = hp;
        atomicAdd(&g_rad[par][b * HH + h], radc);
    }
}

// ---------------------------------------------------------------------------
// Final projection (fp32 SIMT, fp16 state input):
// radout[b,j] += sum_r |(row_r) @ (diag(lam) W_o)[:,j]|
// ---------------------------------------------------------------------------
__global__ void __launch_bounds__(256, 2)
final_gemm_kernel(const float* __restrict__ W_o, int M, int pp)
{
    int b = blockIdx.y;
    int mtile = blockIdx.x;
    const __half* A = g_state[pp] + (size_t)b * EMAX * HH;
    const float* lam = g_lam + b * HH;

    __shared__ float sA[16][132];
    __shared__ float sW[16][64];

    int tid = threadIdx.x;
    int tx = tid & 7, ty = tid >> 3;
    int arow = tid >> 2, acol = (tid & 3) * 4;   // acol in halves (0,4,8,12)
    int wk = tid >> 4, wj = (tid & 15) * 4;

    float acc[4][8];
#pragma unroll
    for (int i = 0; i < 4; i++)
#pragma unroll
        for (int j = 0; j < 8; j++) acc[i][j] = 0.f;

    for (int c = 0; c < 16; c++) {
#pragma unroll
        for (int i = 0; i < 2; i++) {
            int rIn = arow + i * 64;
            uint2 raw = *(const uint2*)&A[(((size_t)mtile * 16 + c) * 128 + rIn) * 16 + acol];
            __half2 p0 = *(__half2*)&raw.x;
            __half2 p1 = *(__half2*)&raw.y;
            sA[acol + 0][rIn] = __half2float(p0.x);
            sA[acol + 1][rIn] = __half2float(p0.y);
            sA[acol + 2][rIn] = __half2float(p1.x);
            sA[acol + 3][rIn] = __half2float(p1.y);
        }
        {
            float lm = lam[c * 16 + wk];
            float4 v = *(const float4*)&W_o[(size_t)(c * 16 + wk) * NOUT + wj];
            v.x *= lm; v.y *= lm; v.z *= lm; v.w *= lm;
            *(float4*)&sW[wk][wj] = v;
        }
        __syncthreads();
#pragma unroll
        for (int k = 0; k < 16; k++) {
            float a[4], wv[8];
            *(float4*)&a[0] = *(const float4*)&sA[k][ty * 4];
            *(float4*)&wv[0] = *(const float4*)&sW[k][tx * 8];
            *(float4*)&wv[4] = *(const float4*)&sW[k][tx * 8 + 4];
#pragma unroll
            for (int i = 0; i < 4; i++)
#pragma unroll
                for (int j = 0; j < 8; j++) acc[i][j] += a[i] * wv[j];
        }
        __syncthreads();
    }

    float cs[8];
#pragma unroll
    for (int j = 0; j < 8; j++) cs[j] = 0.f;
#pragma unroll
    for (int i = 0; i < 4; i++)
#pragma unroll
        for (int j = 0; j < 8; j++) cs[j] += fabsf(acc[i][j]);

    __shared__ float red[32][64];
#pragma unroll
    for (int j = 0; j < 8; j++) red[ty][tx * 8 + j] = cs[j];
    __syncthreads();
    if (tid < NOUT) {
        float s = 0.f;
#pragma unroll
        for (int r = 0; r < 32; r++) s += red[r][tid];
        atomicAdd(&g_radout[b * NOUT + tid], s);
    }
}

// ---------------------------------------------------------------------------
// Combine
// ---------------------------------------------------------------------------
__global__ void combine_kernel(const float* __restrict__ W_o,
                               const float* __restrict__ b_o,
                               float* __restrict__ out)
{
    int b = blockIdx.x, j = threadIdx.x;
    float head = b_o[j];
    float radd = 0.f;
#pragma unroll 8
    for (int k = 0; k < HH; k++) {
        float wv = W_o[k * NOUT + j];
        head += g_headpost[b * HH + k] * wv;
        radd += fabsf(g_delta[b * HH + k]) * fabsf(wv);
    }
    float r = g_radout[b * NOUT + j] + radd;
    out[b * NOUT + j]             = head - r;
    out[BB * NOUT + b * NOUT + j] = head + r;
}

// ---------------------------------------------------------------------------
extern "C" void kernel_launch(void* const* d_in, const int* in_sizes, int n_in,
                              void* d_out, int out_size)
{
    const float* X    = (const float*)d_in[0];
    const float* eps  = (const float*)d_in[1];
    const float* W_ih = (const float*)d_in[2];
    const float* W_hh = (const float*)d_in[3];
    const float* b_ih = (const float*)d_in[4];
    const float* b_hh = (const float*)d_in[5];
    const float* W_o  = (const float*)d_in[6];
    const float* b_o  = (const float*)d_in[7];
    float* out = (float*)d_out;

    cudaFuncSetAttribute(gemm_mma_kernel,
                         cudaFuncAttributeMaxDynamicSharedMemorySize, GT_SMEM);

    step0_kernel<<<BB, HH>>>(X, eps, W_ih, b_ih, b_hh);
    post_kernel<<<dim3(BB, 9), 256>>>(W_hh, 0, 0);     // reads rad[0], zeroes rad[1]

    int E = NIN;
    int pp = 0;
    for (int t = 1; t < TT; t++) {
        int par = t & 1;
        dim3 g((E + 127) / 128, 2, BB);
        gemm_mma_kernel<<<g, 256, GT_SMEM>>>(E, pp, par);
        append_kernel<<<dim3(BB, 10), 256>>>(X, eps, W_ih, W_hh, b_ih, b_hh, t, E, pp, par);
        post_kernel<<<dim3(BB, 9), 256>>>(W_hh, par, (t == TT - 1) ? 1 : 0);
        E += HH + NIN;
        pp ^= 1;
    }

    // E == 9984 == 78*128
    final_gemm_kernel<<<dim3(NTILES, BB), 256>>>(W_o, E, pp);
    combine_kernel<<<BB, NOUT>>>(W_o, b_o, out);
}

// round 10
// speedup vs baseline: 4.1530x; 1.1567x over previous
#include <cuda_runtime.h>
#include <cuda_fp16.h>
#include <math.h>
#include <stdint.h>

// Problem constants
#define TT   32
#define BB   32
#define NIN  64
#define HH   256
#define NOUT 64
#define EMAX 9984          // 78 * 128 exactly
#define NTILES 78
#define CLMIN (-2.0f)
#define CLMAX ( 2.0f)

// ------- device state (no allocations allowed) -------
// Error-row state, fp16, tiled: idx = ((tile*16 + chunk)*128 + row)*16 + h
__device__ __half g_state[2][(size_t)BB * EMAX * HH];
// B' = fp16(lam ⊙ W_hh^T), smem-image (pitch 24 halves):
__device__ __half g_Bp[(size_t)BB * 2 * 16 * 3072];
// B'o = fp16(lam_31 ⊙ W_o), [b][chunk16][row64][pitch24]
__device__ __half g_Bo[(size_t)BB * 16 * 64 * 24];
__device__ float g_rad[2][BB * HH];       // parity ping-pong
__device__ float g_headpre[2][BB * HH];   // parity ping-pong
__device__ float g_delta[BB * HH];
__device__ float g_headpost[BB * HH];
__device__ float g_radout[BB * NOUT];

// ------- helpers -------
__device__ __forceinline__ uint32_t smem_u32(const void* p) {
    uint32_t a;
    asm("{ .reg .u64 t; cvta.to.shared.u64 t, %1; cvt.u32.u64 %0, t; }" : "=r"(a) : "l"(p));
    return a;
}
__device__ __forceinline__ void ldsm4(unsigned r[4], uint32_t addr) {
    asm volatile("ldmatrix.sync.aligned.m8n8.x4.shared.b16 {%0,%1,%2,%3}, [%4];"
                 : "=r"(r[0]), "=r"(r[1]), "=r"(r[2]), "=r"(r[3]) : "r"(addr));
}
__device__ __forceinline__ void mma_f16(float* c, const unsigned a[4],
                                        unsigned b0, unsigned b1) {
    asm volatile("mma.sync.aligned.m16n8k16.row.col.f32.f16.f16.f32 "
                 "{%0,%1,%2,%3},{%4,%5,%6,%7},{%8,%9},{%0,%1,%2,%3};"
                 : "+f"(c[0]), "+f"(c[1]), "+f"(c[2]), "+f"(c[3])
                 : "r"(a[0]), "r"(a[1]), "r"(a[2]), "r"(a[3]), "r"(b0), "r"(b1));
}
__device__ __forceinline__ void cpa16(uint32_t dst, const void* src) {
    asm volatile("cp.async.cg.shared.global [%0], [%1], 16;" :: "r"(dst), "l"(src));
}
// DeepZ tanh transformer pieces from (head, rad)
__device__ __forceinline__ void deepz(float head, float rad,
                                      float& lam, float& mu, float& delta) {
    float l = head - rad, u = head + rad;
    float tl = tanhf(l), tu = tanhf(u);
    lam = fminf(1.f - tl * tl, 1.f - tu * tu);
    mu    = 0.5f * (tu + tl - lam * (u + l));
    delta = 0.5f * (tu - tl - lam * (u - l));
}

#define TILE_BYTES 6144      // 128 rows * 48B pitch
#define STG_BYTES  12288
#define GT_SMEM    (3 * STG_BYTES)
#define FIN_STG    9216      // A 6144 + B 3072
#define FIN_SMEM   (3 * FIN_STG)

// ---------------------------------------------------------------------------
// Step 0: initial x-block rows (fp16 tiled), head_pre_0, rad[0]
// ---------------------------------------------------------------------------
__global__ void step0_kernel(const float* __restrict__ X,
                             const float* __restrict__ eps,
                             const float* __restrict__ W_ih,
                             const float* __restrict__ b_ih,
                             const float* __restrict__ b_hh)
{
    int b = blockIdx.x;
    int tid = threadIdx.x;
    __shared__ float s_hx[NIN], s_w[NIN];
    if (tid < NIN) {
        float x = X[b * NIN + tid];
        float e = eps[b];
        float l = fmaxf(x - e, CLMIN);
        float u = fminf(x + e, CLMAX);
        s_hx[tid] = 0.5f * (l + u);
        s_w[tid]  = 0.5f * (u - l);
    }
    __syncthreads();
    int h = tid;
    float hp = b_ih[h] + b_hh[h];
    float rad = 0.f;
    __half* st = g_state[0] + (size_t)b * EMAX * HH;
    int chunk = h >> 4, kh = h & 15;
#pragma unroll 8
    for (int i = 0; i < NIN; i++) {
        float wv = W_ih[i * HH + h];
        float rowv = s_w[i] * wv;
        hp += s_hx[i] * wv;
        __half hv = __float2half_rn(rowv);
        rad += fabsf(__half2float(hv));
        st[((size_t)chunk * 128 + i) * 16 + kh] = hv;
    }
    g_headpre[0][b * HH + h] = hp;
    g_rad[0][b * HH + h] = rad;
}

// ---------------------------------------------------------------------------
// post_kernel: B' prep (lam_{t-1} ⊙ W_hh) + zero rad[pp^1]. grid (BB, 9).
// ---------------------------------------------------------------------------
__global__ void post_kernel(const float* __restrict__ W_hh, int pp)
{
    int b = blockIdx.x, z = blockIdx.y, tid = threadIdx.x;
    if (z == 8) {
        g_rad[pp ^ 1][b * HH + tid] = 0.f;
        return;
    }
    __shared__ float s_lam[32];
    if (tid < 32) {
        int k = z * 32 + tid;
        float lam, mu, de;
        deepz(g_headpre[pp][b * HH + k], g_rad[pp][b * HH + k], lam, mu, de);
        s_lam[tid] = lam;
    }
    __syncthreads();
    int n = tid;
    int nh = n >> 7, row = n & 127;
#pragma unroll 4
    for (int i = 0; i < 32; i++) {
        int k = z * 32 + i;
        float v = s_lam[i] * W_hh[k * HH + n];
        g_Bp[((size_t)(b * 2 + nh) * 16 + (k >> 4)) * 3072 + row * 24 + (k & 15)]
            = __float2half_rn(v);
    }
}

// ---------------------------------------------------------------------------
// Fused step kernel: gemm tiles + fresh/x row append + head/rad recurrence.
// grid (mtiles + 2, 2, BB), 256 threads.
// reads: state[pp], headpre[pp], rad[pp], B' (prepped)
// writes: state[pp^1], rad[pp^1] (atomics), headpre[pp^1]
// ---------------------------------------------------------------------------
__global__ void __launch_bounds__(256, 2)
step_kernel(const float* __restrict__ X,
            const float* __restrict__ eps,
            const float* __restrict__ W_ih,
            const float* __restrict__ W_hh,
            const float* __restrict__ b_ih,
            const float* __restrict__ b_hh,
            int t, int Eprev, int pp)
{
    extern __shared__ char sm[];
    int b = blockIdx.z;
    int nhalf = blockIdx.y;
    int nbase = nhalf * 128;
    int tid = threadIdx.x;
    int mtiles = gridDim.x - 2;
    int bx = blockIdx.x;
    int par = pp ^ 1;
    const float* Xt = X + (size_t)t * BB * NIN;
    __half* O = g_state[par] + (size_t)b * EMAX * HH;

    if (bx == mtiles) {
        // ---- fresh diag rows + x rows for cols [nbase, nbase+128) ----
        float* sd = (float*)sm;            // 256 delta
        float* sw = (float*)sm + 256;      // 64 x-widths
        {
            float lam, mu, de;
            deepz(g_headpre[pp][b * HH + tid], g_rad[pp][b * HH + tid], lam, mu, de);
            sd[tid] = de;
        }
        if (tid < NIN) {
            float x = Xt[b * NIN + tid];
            float e = eps[b];
            float l = fmaxf(x - e, CLMIN), u = fminf(x + e, CLMAX);
            sw[tid] = 0.5f * (u - l);
        }
        __syncthreads();
#pragma unroll 4
        for (int e = tid; e < 256 * 128; e += 256) {
            int i = e >> 7, h = nbase + (e & 127);
            int R = Eprev + i;
            O[(((size_t)(R >> 7) * 16 + (h >> 4)) * 128 + (R & 127)) * 16 + (h & 15)]
                = __float2half_rn(sd[i] * W_hh[i * HH + h]);
        }
#pragma unroll 4
        for (int e = tid; e < 64 * 128; e += 256) {
            int i = e >> 7, h = nbase + (e & 127);
            int R = Eprev + 256 + i;
            O[(((size_t)(R >> 7) * 16 + (h >> 4)) * 128 + (R & 127)) * 16 + (h & 15)]
                = __float2half_rn(sw[i] * W_ih[i * HH + h]);
        }
        return;
    }
    if (bx == mtiles + 1) {
        // ---- head recurrence + fresh/x rad contributions, h in [nbase,+128) ----
        float* shp = (float*)sm;           // 256 headpost
        float* sdd = (float*)sm + 256;     // 256 |delta|
        float* shx = (float*)sm + 512;     // 64
        float* sw  = (float*)sm + 576;     // 64
        float* red = (float*)sm + 640;     // 512 reduction
        {
            float lam, mu, de;
            float hp0 = g_headpre[pp][b * HH + tid];
            deepz(hp0, g_rad[pp][b * HH + tid], lam, mu, de);
            shp[tid] = lam * hp0 + mu;
            sdd[tid] = fabsf(de);
        }
        if (tid < NIN) {
            float x = Xt[b * NIN + tid];
            float e = eps[b];
            float l = fmaxf(x - e, CLMIN), u = fminf(x + e, CLMAX);
            shx[tid] = 0.5f * (l + u);
            sw[tid]  = 0.5f * (u - l);
        }
        __syncthreads();
        int h = nbase + (tid & 127);
        int seg = tid >> 7;
        float hp = 0.f, radc = 0.f;
        int k0 = seg * 128;
#pragma unroll 8
        for (int k = k0; k < k0 + 128; k++) {
            float wv = W_hh[k * HH + h];
            hp   += shp[k] * wv;
            radc += sdd[k] * fabsf(wv);
        }
        if (seg == 1) {
#pragma unroll 8
            for (int i = 0; i < NIN; i++) {
                float wv = W_ih[i * HH + h];
                hp   += shx[i] * wv;
                radc += sw[i] * fabsf(wv);
            }
        } else {
            hp += b_ih[h] + b_hh[h];
        }
        red[tid] = hp;
        red[tid + 256] = radc;
        __syncthreads();
        if (tid < 128) {
            float hpt = red[tid] + red[tid + 128];
            float rct = red[tid + 256] + red[tid + 384];
            g_headpre[par][b * HH + h] = hpt;
            atomicAdd(&g_rad[par][b * HH + h], rct);
        }
        return;
    }

    // ---- gemm tile path ----
    uint32_t smb = smem_u32(sm);
    int mtile = bx;
    int mbase = mtile * 128;
    int M = Eprev;
    const __half* A = g_state[pp] + (size_t)b * EMAX * HH;
    const __half* Bp = g_Bp + (size_t)(b * 2 + nhalf) * 16 * 3072;

    int w = tid >> 5, lane = tid & 31;
    int aRow = tid >> 1, aHalf = tid & 1;
    int bRow0 = tid / 3, bPart0 = tid - bRow0 * 3;
    int g1 = 256 + tid;
    int bRow1 = g1 / 3, bPart1 = g1 - bRow1 * 3;

#define ISSUE(c) do {                                                          \
    int _s = (c) % 3;                                                          \
    uint32_t _sa = smb + _s * STG_BYTES;                                       \
    cpa16(_sa + aRow * 48 + aHalf * 16,                                        \
          A + (((size_t)mtile * 16 + (c)) * 128 + aRow) * 16 + aHalf * 8);     \
    uint32_t _sb = _sa + TILE_BYTES;                                           \
    cpa16(_sb + bRow0 * 48 + bPart0 * 16,                                      \
          Bp + (size_t)(c) * 3072 + bRow0 * 24 + bPart0 * 8);                  \
    if (tid < 128)                                                             \
        cpa16(_sb + bRow1 * 48 + bPart1 * 16,                                  \
              Bp + (size_t)(c) * 3072 + bRow1 * 24 + bPart1 * 8);              \
    asm volatile("cp.async.commit_group;");                                    \
} while (0)

    float acc[2][8][4];
#pragma unroll
    for (int mt = 0; mt < 2; mt++)
#pragma unroll
        for (int nt = 0; nt < 8; nt++)
#pragma unroll
            for (int e = 0; e < 4; e++) acc[mt][nt][e] = 0.f;

    ISSUE(0);
    ISSUE(1);

    int wm = w >> 1, wn = w & 1;
    uint32_t aL = (uint32_t)((wm * 32 + (lane & 15)) * 48 + ((lane >> 4) << 4));
    uint32_t bL = (uint32_t)((wn * 64 + (lane & 15)) * 48 + ((lane >> 4) << 4));

    for (int c = 0; c < 16; c++) {
        asm volatile("cp.async.wait_group 1;");
        __syncthreads();
        if (c < 14) ISSUE(c + 2);

        int s = c % 3;
        uint32_t aB = smb + s * STG_BYTES + aL;
        uint32_t bB = smb + s * STG_BYTES + TILE_BYTES + bL;

        unsigned af[2][4];
        ldsm4(af[0], aB);
        ldsm4(af[1], aB + 16 * 48);
#pragma unroll
        for (int p = 0; p < 4; p++) {
            unsigned bf[4];
            ldsm4(bf, bB + p * (16 * 48));
#pragma unroll
            for (int mt = 0; mt < 2; mt++) {
                mma_f16(acc[mt][2 * p],     af[mt], bf[0], bf[2]);
                mma_f16(acc[mt][2 * p + 1], af[mt], bf[1], bf[3]);
            }
        }
    }
#undef ISSUE

    float pc[8][2];
#pragma unroll
    for (int nt = 0; nt < 8; nt++) { pc[nt][0] = 0.f; pc[nt][1] = 0.f; }

#pragma unroll
    for (int mt = 0; mt < 2; mt++) {
#pragma unroll
        for (int rr = 0; rr < 2; rr++) {
            int rIn = wm * 32 + mt * 16 + rr * 8 + (lane >> 2);
            int row = mbase + rIn;
            bool ok = (row < M);
#pragma unroll
            for (int nt = 0; nt < 8; nt++) {
                float v0 = acc[mt][nt][rr * 2], v1 = acc[mt][nt][rr * 2 + 1];
                if (ok) {
                    int col = nbase + wn * 64 + nt * 8 + (lane & 3) * 2;
                    __half2 hv = __floats2half2_rn(v0, v1);
                    *(__half2*)&O[(((size_t)mtile * 16 + (col >> 4)) * 128 + rIn) * 16
                                  + (col & 15)] = hv;
                    pc[nt][0] += fabsf(v0);
                    pc[nt][1] += fabsf(v1);
                }
            }
        }
    }
#pragma unroll
    for (int nt = 0; nt < 8; nt++) {
#pragma unroll
        for (int j = 0; j < 2; j++) {
            float s = pc[nt][j];
            s += __shfl_xor_sync(0xFFFFFFFFu, s, 4);
            s += __shfl_xor_sync(0xFFFFFFFFu, s, 8);
            s += __shfl_xor_sync(0xFFFFFFFFu, s, 16);
            pc[nt][j] = s;
        }
    }
    if (lane < 4) {
#pragma unroll
        for (int nt = 0; nt < 8; nt++)
#pragma unroll
            for (int j = 0; j < 2; j++)
                atomicAdd(&g_rad[par][b * HH + nbase + wn * 64 + nt * 8 + lane * 2 + j],
                          pc[nt][j]);
    }
}

// ---------------------------------------------------------------------------
// prep_final: lam_31/delta_31/headpost_31, zero radout, fill B'o = lam⊙W_o.
// grid (BB, 9). Reads headpre[1], rad[1].
// ---------------------------------------------------------------------------
__global__ void prep_final_kernel(const float* __restrict__ W_o)
{
    int b = blockIdx.x, z = blockIdx.y, tid = threadIdx.x;
    if (z == 8) {
        float lam, mu, de;
        float hp0 = g_headpre[1][b * HH + tid];
        deepz(hp0, g_rad[1][b * HH + tid], lam, mu, de);
        g_headpost[b * HH + tid] = lam * hp0 + mu;
        g_delta[b * HH + tid] = de;
        if (tid < NOUT) g_radout[b * NOUT + tid] = 0.f;
        return;
    }
    __shared__ float s_lam[32];
    if (tid < 32) {
        int k = z * 32 + tid;
        float lam, mu, de;
        deepz(g_headpre[1][b * HH + k], g_rad[1][b * HH + k], lam, mu, de);
        s_lam[tid] = lam;
    }
    __syncthreads();
    int n = tid & 63;
    int kb = tid >> 6;   // 0..3
#pragma unroll
    for (int j = 0; j < 8; j++) {
        int kk = kb + j * 4;           // 0..31
        int k = z * 32 + kk;
        float v = s_lam[kk] * W_o[k * NOUT + n];
        g_Bo[(((size_t)b * 16 + (k >> 4)) * 64 + n) * 24 + (k & 15)]
            = __float2half_rn(v);
    }
}

// ---------------------------------------------------------------------------
// Final projection via fp16 MMA: radout[b,j] += sum_r |row_r @ B'o[:,j]|
// grid (78, BB), 256 threads.
// ---------------------------------------------------------------------------
__global__ void __launch_bounds__(256, 2)
final_mma_kernel()
{
    extern __shared__ char sm[];
    uint32_t smb = smem_u32(sm);
    int b = blockIdx.y;
    int mtile = blockIdx.x;
    const __half* A = g_state[1] + (size_t)b * EMAX * HH;
    const __half* Bo = g_Bo + (size_t)b * 16 * 1536;

    int tid = threadIdx.x;
    int w = tid >> 5, lane = tid & 31;
    int aRow = tid >> 1, aHalf = tid & 1;
    int bRow = tid / 3, bPart = tid - bRow * 3;   // tid<192 valid

#define FISSUE(c) do {                                                         \
    int _s = (c) % 3;                                                          \
    uint32_t _sa = smb + _s * FIN_STG;                                         \
    cpa16(_sa + aRow * 48 + aHalf * 16,                                        \
          A + (((size_t)mtile * 16 + (c)) * 128 + aRow) * 16 + aHalf * 8);     \
    if (tid < 192)                                                             \
        cpa16(_sa + TILE_BYTES + bRow * 48 + bPart * 16,                       \
              Bo + (size_t)(c) * 1536 + bRow * 24 + bPart * 8);                \
    asm volatile("cp.async.commit_group;");                                    \
} while (0)

    float acc[8][4];
#pragma unroll
    for (int nt = 0; nt < 8; nt++)
#pragma unroll
        for (int e = 0; e < 4; e++) acc[nt][e] = 0.f;

    FISSUE(0);
    FISSUE(1);

    uint32_t aL = (uint32_t)((w * 16 + (lane & 15)) * 48 + ((lane >> 4) << 4));
    uint32_t bL = (uint32_t)(((lane & 15)) * 48 + ((lane >> 4) << 4));

    for (int c = 0; c < 16; c++) {
        asm volatile("cp.async.wait_group 1;");
        __syncthreads();
        if (c < 14) FISSUE(c + 2);

        int s = c % 3;
        uint32_t aB = smb + s * FIN_STG + aL;
        uint32_t bB = smb + s * FIN_STG + TILE_BYTES + bL;

        unsigned af[4];
        ldsm4(af, aB);
#pragma unroll
        for (int p = 0; p < 4; p++) {
            unsigned bf[4];
            ldsm4(bf, bB + p * (16 * 48));
            mma_f16(acc[2 * p],     af, bf[0], bf[2]);
            mma_f16(acc[2 * p + 1], af, bf[1], bf[3]);
        }
    }
#undef FISSUE

    float pc[8][2];
#pragma unroll
    for (int nt = 0; nt < 8; nt++) {
        pc[nt][0] = fabsf(acc[nt][0]) + fabsf(acc[nt][2]);
        pc[nt][1] = fabsf(acc[nt][1]) + fabsf(acc[nt][3]);
    }
#pragma unroll
    for (int nt = 0; nt < 8; nt++) {
#pragma unroll
        for (int j = 0; j < 2; j++) {
            float s = pc[nt][j];
            s += __shfl_xor_sync(0xFFFFFFFFu, s, 4);
            s += __shfl_xor_sync(0xFFFFFFFFu, s, 8);
            s += __shfl_xor_sync(0xFFFFFFFFu, s, 16);
            pc[nt][j] = s;
        }
    }
    if (lane < 4) {
#pragma unroll
        for (int nt = 0; nt < 8; nt++)
#pragma unroll
            for (int j = 0; j < 2; j++)
                atomicAdd(&g_radout[b * NOUT + nt * 8 + lane * 2 + j], pc[nt][j]);
    }
}

// ---------------------------------------------------------------------------
// Combine
// ---------------------------------------------------------------------------
__global__ void combine_kernel(const float* __restrict__ W_o,
                               const float* __restrict__ b_o,
                               float* __restrict__ out)
{
    int b = blockIdx.x, j = threadIdx.x;
    float head = b_o[j];
    float radd = 0.f;
#pragma unroll 8
    for (int k = 0; k < HH; k++) {
        float wv = W_o[k * NOUT + j];
        head += g_headpost[b * HH + k] * wv;
        radd += fabsf(g_delta[b * HH + k]) * fabsf(wv);
    }
    float r = g_radout[b * NOUT + j] + radd;
    out[b * NOUT + j]             = head - r;
    out[BB * NOUT + b * NOUT + j] = head + r;
}

// ---------------------------------------------------------------------------
extern "C" void kernel_launch(void* const* d_in, const int* in_sizes, int n_in,
                              void* d_out, int out_size)
{
    const float* X    = (const float*)d_in[0];
    const float* eps  = (const float*)d_in[1];
    const float* W_ih = (const float*)d_in[2];
    const float* W_hh = (const float*)d_in[3];
    const float* b_ih = (const float*)d_in[4];
    const float* b_hh = (const float*)d_in[5];
    const float* W_o  = (const float*)d_in[6];
    const float* b_o  = (const float*)d_in[7];
    float* out = (float*)d_out;

    cudaFuncSetAttribute(step_kernel,
                         cudaFuncAttributeMaxDynamicSharedMemorySize, GT_SMEM);
    cudaFuncSetAttribute(final_mma_kernel,
                         cudaFuncAttributeMaxDynamicSharedMemorySize, FIN_SMEM);

    step0_kernel<<<BB, HH>>>(X, eps, W_ih, b_ih, b_hh);

    int E = NIN;
    for (int t = 1; t < TT; t++) {
        int pp = (t - 1) & 1;
        int mtiles = (E + 127) / 128;
        post_kernel<<<dim3(BB, 9), 256>>>(W_hh, pp);
        step_kernel<<<dim3(mtiles + 2, 2, BB), 256, GT_SMEM>>>(
            X, eps, W_ih, W_hh, b_ih, b_hh, t, E, pp);
        E += HH + NIN;
    }

    // E == 9984, state in g_state[1], headpre/rad parity 1
    prep_final_kernel<<<dim3(BB, 9), 256>>>(W_o);
    final_mma_kernel<<<dim3(NTILES, BB), 256, FIN_SMEM>>>();
    combine_kernel<<<BB, NOUT>>>(W_o, b_o, out);
}